// round 1
// baseline (speedup 1.0000x reference)
#include <cuda_runtime.h>
#include <math.h>

#define B_TOTAL   32768
#define NJ        33
#define FD        64
#define NG        192          // 3*FD gate width
#define NB        6            // batch elements per CTA
#define ROWS_SLOT 34           // 33 joints + 1 dummy row (pair alignment)
#define ROWS_PAD  (NB*ROWS_SLOT)   // 204
#define NTHREADS  384          // 64 d-lanes * 6 slots

// ---------------- constant neighbor tables (self + edges) ----------------
__constant__ int c_nbr[NJ][4] = {
    {0,0,0,0},{1,0,0,0},{2,0,0,0},{3,0,0,0},{4,0,0,0},{5,0,0,0},{6,0,0,0},
    {7,0,0,0},{8,0,0,0},{9,0,0,0},{10,0,0,0},
    {11,12,23,13},{12,11,24,14},{13,11,15,0},{14,12,16,0},{15,13,0,0},{16,14,0,0},
    {17,0,0,0},{18,0,0,0},{19,0,0,0},{20,0,0,0},{21,0,0,0},{22,0,0,0},
    {23,11,24,25},{24,12,23,26},{25,23,27,0},{26,24,28,0},{27,25,0,0},{28,26,0,0},
    {29,0,0,0},{30,0,0,0},{31,0,0,0},{32,0,0,0}
};
__constant__ int c_cnt[NJ] = {1,1,1,1,1,1,1,1,1,1,1,
                              4,4,3,3,2,2,
                              1,1,1,1,1,1,
                              4,4,3,3,2,2,
                              1,1,1,1};
__constant__ float c_invcnt[NJ] = {1.f,1.f,1.f,1.f,1.f,1.f,1.f,1.f,1.f,1.f,1.f,
                                   0.25f,0.25f,1.f/3.f,1.f/3.f,0.5f,0.5f,
                                   1.f,1.f,1.f,1.f,1.f,1.f,
                                   0.25f,0.25f,1.f/3.f,1.f/3.f,0.5f,0.5f,
                                   1.f,1.f,1.f,1.f};

// ---------------- fused weights (device scratch, written by prep kernel) ----------------
__device__ __align__(16) float g_WA[FD*NG];   // WA[k][e] = sum_f msg_w[f,k] * w_ih[e,f]
__device__ __align__(16) float g_WH[FD*NG];   // WH[k][e] = w_hh[e,k]
__device__ float g_biasR[FD], g_biasZ[FD], g_biasIN[FD], g_biasHN[FD];

// ---------------- f32x2 helpers (sm_100+ packed fp32) ----------------
typedef unsigned long long u64;

__device__ __forceinline__ u64 ffma2(u64 a, u64 b, u64 c) {
    u64 d;
    asm("fma.rn.f32x2 %0, %1, %2, %3;" : "=l"(d) : "l"(a), "l"(b), "l"(c));
    return d;
}
__device__ __forceinline__ u64 dup2(float x) {
    u64 r;
    asm("mov.b64 %0, {%1, %2};" : "=l"(r) : "f"(x), "f"(x));
    return r;
}
__device__ __forceinline__ float2 unpack2(u64 v) {
    float2 r;
    asm("mov.b64 {%0, %1}, %2;" : "=f"(r.x), "=f"(r.y) : "l"(v));
    return r;
}
__device__ __forceinline__ u64 lds2(const float* p) {
    return *reinterpret_cast<const u64*>(p);   // 8B-aligned by construction -> LDS.64
}
__device__ __forceinline__ float sigmoidf_(float x) {
    return 1.0f / (1.0f + __expf(-x));
}

// ---------------- prologue: fold linear chain into WA/WH + biases ----------------
__global__ void prep_kernel(const float* __restrict__ msg_w, const float* __restrict__ msg_b,
                            const float* __restrict__ w_ih, const float* __restrict__ w_hh,
                            const float* __restrict__ b_ih, const float* __restrict__ b_hh) {
    int t = blockIdx.x * blockDim.x + threadIdx.x;
    int stride = gridDim.x * blockDim.x;
    for (int idx = t; idx < FD*NG; idx += stride) {
        int k = idx / NG;        // input feature dim
        int e = idx - k * NG;    // gate output dim (0..191)
        float s = 0.f;
        #pragma unroll 8
        for (int f = 0; f < FD; f++)
            s += msg_w[f*FD + k] * w_ih[e*FD + f];
        g_WA[idx] = s;
        g_WH[idx] = w_hh[e*FD + k];
    }
    for (int e = t; e < NG; e += stride) {
        float s = 0.f;
        #pragma unroll 8
        for (int f = 0; f < FD; f++)
            s += msg_b[f] * w_ih[e*FD + f];
        float bA = s + b_ih[e];
        int d = e & 63;
        if (e < 64)        g_biasR[d]  = bA + b_hh[e];
        else if (e < 128)  g_biasZ[d]  = bA + b_hh[e];
        else             { g_biasIN[d] = bA; g_biasHN[d] = b_hh[e]; }
    }
}

// ---------------- smem layout (floats) ----------------
#define OFF_AGG 0
#define OFF_H   (FD*ROWS_PAD)                 // 13056
#define OFF_WA  (2*FD*ROWS_PAD)               // 26112
#define OFF_WH  (2*FD*ROWS_PAD + FD*NG)       // 38400
#define OFF_VIS (2*FD*ROWS_PAD + 2*FD*NG)     // 50688
#define SMEM_FLOATS (OFF_VIS + 256)           // 50944
#define SMEM_BYTES  (SMEM_FLOATS * 4)         // 203776

// GEMM chunk over P row-pairs: acc(r_sum, z_sum, i_n, h_n) per pair
template<int P>
__device__ __forceinline__ void gemm_chunk(
    const float* __restrict__ sAgg, const float* __restrict__ sH,
    const float* __restrict__ sWA,  const float* __restrict__ sWH,
    int d, int rbase, int p0,
    bool valid, float* __restrict__ out, long long obase)
{
    u64 accR[P], accZ[P], accN[P], accHN[P];
    #pragma unroll
    for (int p = 0; p < P; p++) { accR[p]=0ull; accZ[p]=0ull; accN[p]=0ull; accHN[p]=0ull; }

    const float* ak0 = sAgg + rbase + 2*p0;
    const float* hk0 = sH   + rbase + 2*p0;

    #pragma unroll 1
    for (int k = 0; k < FD; ++k) {
        const float* wAk = sWA + k*NG + d;
        const float* wHk = sWH + k*NG + d;
        u64 wAr = dup2(wAk[0]);
        u64 wAz = dup2(wAk[64]);
        u64 wAn = dup2(wAk[128]);
        u64 wHr = dup2(wHk[0]);
        u64 wHz = dup2(wHk[64]);
        u64 wHn = dup2(wHk[128]);
        const float* ak = ak0 + k*ROWS_PAD;
        const float* hk = hk0 + k*ROWS_PAD;
        #pragma unroll
        for (int p = 0; p < P; p++) {
            u64 a2 = lds2(ak + 2*p);
            u64 h2 = lds2(hk + 2*p);
            accR[p]  = ffma2(a2, wAr, accR[p]);
            accR[p]  = ffma2(h2, wHr, accR[p]);
            accZ[p]  = ffma2(a2, wAz, accZ[p]);
            accZ[p]  = ffma2(h2, wHz, accZ[p]);
            accN[p]  = ffma2(a2, wAn, accN[p]);
            accHN[p] = ffma2(h2, wHn, accHN[p]);
        }
    }

    float bR  = g_biasR[d];
    float bZ  = g_biasZ[d];
    float bIN = g_biasIN[d];
    float bHN = g_biasHN[d];

    #pragma unroll
    for (int p = 0; p < P; p++) {
        float2 rs = unpack2(accR[p]);
        float2 zs = unpack2(accZ[p]);
        float2 in = unpack2(accN[p]);
        float2 hn = unpack2(accHN[p]);
        #pragma unroll
        for (int half = 0; half < 2; half++) {
            int j = 2*(p0+p) + half;
            if (j >= NJ) continue;
            float rsum = (half ? rs.y : rs.x) + bR;
            float zsum = (half ? zs.y : zs.x) + bZ;
            float inn  = (half ? in.y : in.x) + bIN;
            float hnn  = (half ? hn.y : hn.x) + bHN;
            float r = sigmoidf_(rsum);
            float z = sigmoidf_(zsum);
            float n = tanhf(inn + r*hnn);
            float h = sH[d*ROWS_PAD + rbase + j];
            float o = (1.0f - z)*n + z*h;
            if (valid) out[obase + (long long)j*FD + d] = o;
        }
    }
}

__global__ void __launch_bounds__(NTHREADS, 1)
skeleton_gnn_kernel(const float* __restrict__ feats,
                    const float* __restrict__ vis,
                    float* __restrict__ out)
{
    extern __shared__ float smem[];
    float* sAgg = smem + OFF_AGG;
    float* sH   = smem + OFF_H;
    float* sWA  = smem + OFF_WA;
    float* sWH  = smem + OFF_WH;
    float* sVis = smem + OFF_VIS;

    const int tid = threadIdx.x;
    const int b0  = blockIdx.x * NB;

    // ---- stage fused weights into smem (vectorized) ----
    {
        const float4* gwa = reinterpret_cast<const float4*>(g_WA);
        const float4* gwh = reinterpret_cast<const float4*>(g_WH);
        float4* swa = reinterpret_cast<float4*>(sWA);
        float4* swh = reinterpret_cast<float4*>(sWH);
        for (int i = tid; i < FD*NG/4; i += NTHREADS) { swa[i] = gwa[i]; swh[i] = gwh[i]; }
    }
    // ---- visibility ----
    for (int i = tid; i < NB*NJ; i += NTHREADS) {
        int s = i / NJ;
        int bb = b0 + s;
        sVis[i] = (bb < B_TOTAL) ? vis[bb*NJ + (i - s*NJ)] : 0.f;
    }
    // ---- feats -> sH transposed [k][row] ----
    for (int i = tid; i < NB*NJ*FD; i += NTHREADS) {
        int k = i & 63;
        int r = i >> 6;                 // 0..197
        int s = r / NJ;
        int j = r - s*NJ;
        int bb = b0 + s;
        float v = (bb < B_TOTAL) ? feats[((long long)bb*NJ + j)*FD + k] : 0.f;
        sH[k*ROWS_PAD + s*ROWS_SLOT + j] = v;
    }
    // ---- zero dummy rows (pair padding) ----
    for (int i = tid; i < NB*FD; i += NTHREADS) {
        int s = i >> 6, k = i & 63;
        sH  [k*ROWS_PAD + s*ROWS_SLOT + NJ] = 0.f;
        sAgg[k*ROWS_PAD + s*ROWS_SLOT + NJ] = 0.f;
    }
    __syncthreads();

    // ---- sparse neighborhood aggregation into sAgg ----
    for (int i = tid; i < NB*NJ*FD; i += NTHREADS) {
        int k = i & 63;
        int r = i >> 6;
        int s = r / NJ;
        int j = r - s*NJ;
        const float* hk = sH + k*ROWS_PAD + s*ROWS_SLOT;
        const float* vv = sVis + s*NJ;
        int cnt = c_cnt[j];
        float sum = 0.f;
        #pragma unroll
        for (int q = 0; q < 4; q++) {
            int nb = c_nbr[j][q];
            float w = (q < cnt) ? vv[nb] : 0.f;
            sum += w * hk[nb];
        }
        sAgg[k*ROWS_PAD + s*ROWS_SLOT + j] = sum * c_invcnt[j];
    }
    __syncthreads();

    // ---- register-blocked GEMM + GRU gates ----
    const int d     = tid & 63;
    const int slot  = tid >> 6;            // 0..5
    const int rbase = slot * ROWS_SLOT;
    const bool valid = (b0 + slot) < B_TOTAL;
    const long long obase = ((long long)(b0 + slot) * NJ) * FD;

    gemm_chunk<9>(sAgg, sH, sWA, sWH, d, rbase, 0, valid, out, obase);
    gemm_chunk<8>(sAgg, sH, sWA, sWH, d, rbase, 9, valid, out, obase);
}

extern "C" void kernel_launch(void* const* d_in, const int* in_sizes, int n_in,
                              void* d_out, int out_size)
{
    const float* feats = (const float*)d_in[0];
    const float* vis   = (const float*)d_in[1];
    const float* msg_w = (const float*)d_in[2];
    const float* msg_b = (const float*)d_in[3];
    const float* w_ih  = (const float*)d_in[4];
    const float* w_hh  = (const float*)d_in[5];
    const float* b_ih  = (const float*)d_in[6];
    const float* b_hh  = (const float*)d_in[7];
    float* out = (float*)d_out;

    cudaFuncSetAttribute(skeleton_gnn_kernel,
                         cudaFuncAttributeMaxDynamicSharedMemorySize, SMEM_BYTES);

    prep_kernel<<<48, 256>>>(msg_w, msg_b, w_ih, w_hh, b_ih, b_hh);

    int grid = (B_TOTAL + NB - 1) / NB;   // 5462
    skeleton_gnn_kernel<<<grid, NTHREADS, SMEM_BYTES>>>(feats, vis, out);
}

// round 3
// speedup vs baseline: 3.0269x; 3.0269x over previous
#include <cuda_runtime.h>
#include <cstdint>

typedef unsigned int u32;

#define NJ        33
#define FD        64
#define B_TOTAL   32768
#define M_TOTAL   (B_TOTAL*NJ)        // 1081344
#define TILE_M    64
#define NTILES    (M_TOTAL/TILE_M)    // 16896
#define GRID_MAIN 148
#define NTHREADS  384

// ---------------- smem layout (float indices) ----------------
#define F_B     0                       // packed B fragments: 24576 floats (96KB)
#define F_A     24576                   // agg tile [64][68]
#define F_H     (24576 + 64*68)         // h   tile [64][68]
#define F_S     (24576 + 2*64*68)       // epilogue exchange [64][260]
#define F_BIAS  (F_S + 64*260)          // 256 floats
#define SMEM_FLOATS (F_BIAS + 256)
#define SMEM_BYTES  (SMEM_FLOATS*4)     // 200704

#define A_STRIDE 68
#define S_STRIDE 260

// ---------------- neighbor tables (self first) ----------------
__constant__ int c_nbr[NJ][4] = {
    {0,0,0,0},{1,0,0,0},{2,0,0,0},{3,0,0,0},{4,0,0,0},{5,0,0,0},{6,0,0,0},
    {7,0,0,0},{8,0,0,0},{9,0,0,0},{10,0,0,0},
    {11,12,23,13},{12,11,24,14},{13,11,15,0},{14,12,16,0},{15,13,0,0},{16,14,0,0},
    {17,0,0,0},{18,0,0,0},{19,0,0,0},{20,0,0,0},{21,0,0,0},{22,0,0,0},
    {23,11,24,25},{24,12,23,26},{25,23,27,0},{26,24,28,0},{27,25,0,0},{28,26,0,0},
    {29,0,0,0},{30,0,0,0},{31,0,0,0},{32,0,0,0}
};
__constant__ int c_cnt[NJ] = {1,1,1,1,1,1,1,1,1,1,1, 4,4,3,3,2,2, 1,1,1,1,1,1,
                              4,4,3,3,2,2, 1,1,1,1};
__constant__ float c_invcnt[NJ] = {1.f,1.f,1.f,1.f,1.f,1.f,1.f,1.f,1.f,1.f,1.f,
                                   0.25f,0.25f,1.f/3.f,1.f/3.f,0.5f,0.5f,
                                   1.f,1.f,1.f,1.f,1.f,1.f,
                                   0.25f,0.25f,1.f/3.f,1.f/3.f,0.5f,0.5f,
                                   1.f,1.f,1.f,1.f};

// fragment-packed fused weights + biases (written by prep kernel)
// layout: float4 slot per (kstep 0..7, nb 0..23, lane 0..31):
//   .x = GA[nb*8+g][ks*8+tig]  .y = GA[..][ks*8+tig+4]
//   .z = GH[nb*8+g][ks*8+tig]  .w = GH[..][ks*8+tig+4]
__device__ __align__(16) float g_Bpack[8*24*32*4];   // 24576 floats
__device__ float g_bias[256];                        // R | Z | IN | HN

// ---------------- helpers ----------------
__device__ __forceinline__ float tf32r(float x) {
    u32 u; asm("cvt.rna.tf32.f32 %0, %1;" : "=r"(u) : "f"(x));
    return __uint_as_float(u);
}
__device__ __forceinline__ float4 tf4(float4 v) {
    return make_float4(tf32r(v.x), tf32r(v.y), tf32r(v.z), tf32r(v.w));
}
__device__ __forceinline__ float tanh_ap(float x) {
    float y; asm("tanh.approx.f32 %0, %1;" : "=f"(y) : "f"(x)); return y;
}
__device__ __forceinline__ float sigm(float x) {
    return 0.5f * tanh_ap(0.5f * x) + 0.5f;
}
__device__ __forceinline__ void mma8(float c[4], u32 a0, u32 a1, u32 a2, u32 a3,
                                     u32 b0, u32 b1) {
    asm volatile("mma.sync.aligned.m16n8k8.row.col.f32.tf32.tf32.f32 "
                 "{%0,%1,%2,%3}, {%4,%5,%6,%7}, {%8,%9}, {%0,%1,%2,%3};"
                 : "+f"(c[0]), "+f"(c[1]), "+f"(c[2]), "+f"(c[3])
                 : "r"(a0), "r"(a1), "r"(a2), "r"(a3), "r"(b0), "r"(b1));
}
__device__ __forceinline__ u32 fbits(float x) { return __float_as_uint(x); }

// ---------------- prep: fold linear chain, pack fragments, tf32-round ----------------
__global__ void prep_kernel(const float* __restrict__ msg_w, const float* __restrict__ msg_b,
                            const float* __restrict__ w_ih, const float* __restrict__ w_hh,
                            const float* __restrict__ b_ih, const float* __restrict__ b_hh) {
    int t = blockIdx.x * blockDim.x + threadIdx.x;
    if (t < 8*24*32) {
        int lane = t & 31;
        int nb   = (t >> 5) % 24;
        int ks   = t / (24*32);
        int g = lane >> 2, tig = lane & 3;
        int n = nb*8 + g;
        int k0 = ks*8 + tig, k1 = k0 + 4;
        float ga0 = 0.f, ga1 = 0.f;
        #pragma unroll 8
        for (int f = 0; f < FD; f++) {
            float wi = w_ih[n*FD + f];
            ga0 += msg_w[f*FD + k0] * wi;
            ga1 += msg_w[f*FD + k1] * wi;
        }
        float4 v = make_float4(tf32r(ga0), tf32r(ga1),
                               tf32r(w_hh[n*FD + k0]), tf32r(w_hh[n*FD + k1]));
        ((float4*)g_Bpack)[t] = v;
    }
    if (t < 192) {
        float s = 0.f;
        #pragma unroll 8
        for (int f = 0; f < FD; f++) s += msg_b[f] * w_ih[t*FD + f];
        float bA = s + b_ih[t];
        if (t < 128)      g_bias[t] = bA + b_hh[t];
        else            { g_bias[t] = bA; g_bias[t + 64] = b_hh[t]; }
    }
}

// ---------------- main persistent fused kernel ----------------
__global__ void __launch_bounds__(NTHREADS, 1)
skeleton_gnn_mma(const float* __restrict__ feats,
                 const float* __restrict__ vis,
                 float* __restrict__ out)
{
    extern __shared__ float sm[];
    const int tid = threadIdx.x;

    // stage packed weights + biases
    {
        const float4* gb = (const float4*)g_Bpack;
        float4* s4 = (float4*)(sm + F_B);
        #pragma unroll
        for (int i = 0; i < 16; i++) s4[tid + i*NTHREADS] = gb[tid + i*NTHREADS];
        if (tid < 256) sm[F_BIAS + tid] = g_bias[tid];
    }
    __syncthreads();

    const int w    = tid >> 5;
    const int lane = tid & 31;
    const int g    = lane >> 2;
    const int tig  = lane & 3;
    const int mrb  = (w / 6) * 32;     // 0 or 32
    const int nidx = w % 6;            // n32 slice
    float* As = sm + F_A;
    float* Ah = sm + F_H;
    float* S  = sm + F_S;
    const float* sbias = sm + F_BIAS;
    const float4* Bp4 = (const float4*)(sm + F_B);

    for (int t = blockIdx.x; t < NTILES; t += GRID_MAIN) {
        const int gr0 = t * TILE_M;

        // ======== phase 1: gather agg + h into smem (tf32-rounded) ========
        if (tid < 256) {
            int row = tid >> 2, q = tid & 3;      // q: 16-k chunk
            int gr = gr0 + row;
            int b = (int)((u32)gr / 33u);
            int j = gr - b*33;
            const float4* fb = (const float4*)feats + (size_t)b*(NJ*FD/4);
            const float4* srow = fb + j*16 + q*4;
            float4 s0 = srow[0], s1 = srow[1], s2 = srow[2], s3 = srow[3];
            float* hp = Ah + row*A_STRIDE + q*16;
            *(float4*)(hp + 0)  = tf4(s0);
            *(float4*)(hp + 4)  = tf4(s1);
            *(float4*)(hp + 8)  = tf4(s2);
            *(float4*)(hp + 12) = tf4(s3);
            float w0 = __ldg(vis + b*NJ + j);
            float4 a0 = make_float4(w0*s0.x, w0*s0.y, w0*s0.z, w0*s0.w);
            float4 a1 = make_float4(w0*s1.x, w0*s1.y, w0*s1.z, w0*s1.w);
            float4 a2 = make_float4(w0*s2.x, w0*s2.y, w0*s2.z, w0*s2.w);
            float4 a3 = make_float4(w0*s3.x, w0*s3.y, w0*s3.z, w0*s3.w);
            int cnt = c_cnt[j];
            #pragma unroll
            for (int qi = 1; qi < 4; ++qi) {
                if (qi < cnt) {
                    int nb = c_nbr[j][qi];
                    float wv = __ldg(vis + b*NJ + nb);
                    const float4* nr = fb + nb*16 + q*4;
                    float4 n0 = nr[0], n1 = nr[1], n2 = nr[2], n3 = nr[3];
                    a0.x += wv*n0.x; a0.y += wv*n0.y; a0.z += wv*n0.z; a0.w += wv*n0.w;
                    a1.x += wv*n1.x; a1.y += wv*n1.y; a1.z += wv*n1.z; a1.w += wv*n1.w;
                    a2.x += wv*n2.x; a2.y += wv*n2.y; a2.z += wv*n2.z; a2.w += wv*n2.w;
                    a3.x += wv*n3.x; a3.y += wv*n3.y; a3.z += wv*n3.z; a3.w += wv*n3.w;
                }
            }
            float ic = c_invcnt[j];
            a0.x*=ic; a0.y*=ic; a0.z*=ic; a0.w*=ic;
            a1.x*=ic; a1.y*=ic; a1.z*=ic; a1.w*=ic;
            a2.x*=ic; a2.y*=ic; a2.z*=ic; a2.w*=ic;
            a3.x*=ic; a3.y*=ic; a3.z*=ic; a3.w*=ic;
            float* ap = As + row*A_STRIDE + q*16;
            *(float4*)(ap + 0)  = tf4(a0);
            *(float4*)(ap + 4)  = tf4(a1);
            *(float4*)(ap + 8)  = tf4(a2);
            *(float4*)(ap + 12) = tf4(a3);
        }
        __syncthreads();

        // ======== phase 2: warp MMA (m32 x n32, dual chains) ========
        if (nidx < 4) {
            // r/z columns: both chains accumulate into one set; bias-init
            float acc[2][4][4];
            #pragma unroll
            for (int mb = 0; mb < 2; mb++)
                #pragma unroll
                for (int nb = 0; nb < 4; nb++) {
                    int col = nidx*32 + nb*8 + 2*tig;
                    float b0 = sbias[col], b1 = sbias[col+1];
                    acc[mb][nb][0] = b0; acc[mb][nb][1] = b1;
                    acc[mb][nb][2] = b0; acc[mb][nb][3] = b1;
                }
            #pragma unroll
            for (int ks = 0; ks < 8; ks++) {
                u32 fa[2][4], fh[2][4];
                #pragma unroll
                for (int mb = 0; mb < 2; mb++) {
                    const int rb = mrb + mb*16;
                    const int kc = ks*8;
                    fa[mb][0] = fbits(As[(rb+g)*A_STRIDE + kc + tig]);
                    fa[mb][1] = fbits(As[(rb+g+8)*A_STRIDE + kc + tig]);
                    fa[mb][2] = fbits(As[(rb+g)*A_STRIDE + kc + tig + 4]);
                    fa[mb][3] = fbits(As[(rb+g+8)*A_STRIDE + kc + tig + 4]);
                    fh[mb][0] = fbits(Ah[(rb+g)*A_STRIDE + kc + tig]);
                    fh[mb][1] = fbits(Ah[(rb+g+8)*A_STRIDE + kc + tig]);
                    fh[mb][2] = fbits(Ah[(rb+g)*A_STRIDE + kc + tig + 4]);
                    fh[mb][3] = fbits(Ah[(rb+g+8)*A_STRIDE + kc + tig + 4]);
                }
                #pragma unroll
                for (int nb = 0; nb < 4; nb++) {
                    float4 bw = Bp4[(ks*24 + nidx*4 + nb)*32 + lane];
                    u32 wa0 = fbits(bw.x), wa1 = fbits(bw.y);
                    u32 wh0 = fbits(bw.z), wh1 = fbits(bw.w);
                    #pragma unroll
                    for (int mb = 0; mb < 2; mb++) {
                        mma8(acc[mb][nb], fa[mb][0], fa[mb][1], fa[mb][2], fa[mb][3], wa0, wa1);
                        mma8(acc[mb][nb], fh[mb][0], fh[mb][1], fh[mb][2], fh[mb][3], wh0, wh1);
                    }
                }
            }
            // epilogue store to S
            #pragma unroll
            for (int mb = 0; mb < 2; mb++) {
                const int rb = mrb + mb*16;
                #pragma unroll
                for (int nb = 0; nb < 4; nb++) {
                    int col = nidx*32 + nb*8 + 2*tig;
                    *(float2*)&S[(rb+g)*S_STRIDE + col]   = make_float2(acc[mb][nb][0], acc[mb][nb][1]);
                    *(float2*)&S[(rb+g+8)*S_STRIDE + col] = make_float2(acc[mb][nb][2], acc[mb][nb][3]);
                }
            }
        } else {
            // n columns: separate in (agg chain) and hn (h chain) accums; bias-init
            float ai[2][4][4], ah[2][4][4];
            #pragma unroll
            for (int mb = 0; mb < 2; mb++)
                #pragma unroll
                for (int nb = 0; nb < 4; nb++) {
                    int col = nidx*32 + nb*8 + 2*tig;   // 128..191
                    float bi0 = sbias[col], bi1 = sbias[col+1];
                    float bh0 = sbias[col+64], bh1 = sbias[col+65];
                    ai[mb][nb][0] = bi0; ai[mb][nb][1] = bi1;
                    ai[mb][nb][2] = bi0; ai[mb][nb][3] = bi1;
                    ah[mb][nb][0] = bh0; ah[mb][nb][1] = bh1;
                    ah[mb][nb][2] = bh0; ah[mb][nb][3] = bh1;
                }
            #pragma unroll
            for (int ks = 0; ks < 8; ks++) {
                u32 fa[2][4], fh[2][4];
                #pragma unroll
                for (int mb = 0; mb < 2; mb++) {
                    const int rb = mrb + mb*16;
                    const int kc = ks*8;
                    fa[mb][0] = fbits(As[(rb+g)*A_STRIDE + kc + tig]);
                    fa[mb][1] = fbits(As[(rb+g+8)*A_STRIDE + kc + tig]);
                    fa[mb][2] = fbits(As[(rb+g)*A_STRIDE + kc + tig + 4]);
                    fa[mb][3] = fbits(As[(rb+g+8)*A_STRIDE + kc + tig + 4]);
                    fh[mb][0] = fbits(Ah[(rb+g)*A_STRIDE + kc + tig]);
                    fh[mb][1] = fbits(Ah[(rb+g+8)*A_STRIDE + kc + tig]);
                    fh[mb][2] = fbits(Ah[(rb+g)*A_STRIDE + kc + tig + 4]);
                    fh[mb][3] = fbits(Ah[(rb+g+8)*A_STRIDE + kc + tig + 4]);
                }
                #pragma unroll
                for (int nb = 0; nb < 4; nb++) {
                    float4 bw = Bp4[(ks*24 + nidx*4 + nb)*32 + lane];
                    u32 wa0 = fbits(bw.x), wa1 = fbits(bw.y);
                    u32 wh0 = fbits(bw.z), wh1 = fbits(bw.w);
                    #pragma unroll
                    for (int mb = 0; mb < 2; mb++) {
                        mma8(ai[mb][nb], fa[mb][0], fa[mb][1], fa[mb][2], fa[mb][3], wa0, wa1);
                        mma8(ah[mb][nb], fh[mb][0], fh[mb][1], fh[mb][2], fh[mb][3], wh0, wh1);
                    }
                }
            }
            #pragma unroll
            for (int mb = 0; mb < 2; mb++) {
                const int rb = mrb + mb*16;
                #pragma unroll
                for (int nb = 0; nb < 4; nb++) {
                    int col = nidx*32 + nb*8 + 2*tig;
                    *(float2*)&S[(rb+g)*S_STRIDE + col]        = make_float2(ai[mb][nb][0], ai[mb][nb][1]);
                    *(float2*)&S[(rb+g+8)*S_STRIDE + col]      = make_float2(ai[mb][nb][2], ai[mb][nb][3]);
                    *(float2*)&S[(rb+g)*S_STRIDE + col + 64]   = make_float2(ah[mb][nb][0], ah[mb][nb][1]);
                    *(float2*)&S[(rb+g+8)*S_STRIDE + col + 64] = make_float2(ah[mb][nb][2], ah[mb][nb][3]);
                }
            }
        }
        __syncthreads();

        // ======== phase 3: gates + store ========
        #pragma unroll
        for (int i = tid; i < 1024; i += NTHREADS) {
            int row = i >> 4;
            int d4  = (i & 15) << 2;
            const float* Sr = S + row*S_STRIDE;
            float4 rv = *(const float4*)(Sr + d4);
            float4 zv = *(const float4*)(Sr + 64 + d4);
            float4 iv = *(const float4*)(Sr + 128 + d4);
            float4 nv = *(const float4*)(Sr + 192 + d4);
            float4 hv = *(const float4*)(feats + (size_t)(gr0 + row)*FD + d4);
            float4 o;
            {
                float r = sigm(rv.x), z = sigm(zv.x);
                float n = tanh_ap(iv.x + r*nv.x);
                o.x = (1.0f - z)*n + z*hv.x;
            }
            {
                float r = sigm(rv.y), z = sigm(zv.y);
                float n = tanh_ap(iv.y + r*nv.y);
                o.y = (1.0f - z)*n + z*hv.y;
            }
            {
                float r = sigm(rv.z), z = sigm(zv.z);
                float n = tanh_ap(iv.z + r*nv.z);
                o.z = (1.0f - z)*n + z*hv.z;
            }
            {
                float r = sigm(rv.w), z = sigm(zv.w);
                float n = tanh_ap(iv.w + r*nv.w);
                o.w = (1.0f - z)*n + z*hv.w;
            }
            *(float4*)(out + (size_t)(gr0 + row)*FD + d4) = o;
        }
        __syncthreads();
    }
}

extern "C" void kernel_launch(void* const* d_in, const int* in_sizes, int n_in,
                              void* d_out, int out_size)
{
    const float* feats = (const float*)d_in[0];
    const float* vis   = (const float*)d_in[1];
    const float* msg_w = (const float*)d_in[2];
    const float* msg_b = (const float*)d_in[3];
    const float* w_ih  = (const float*)d_in[4];
    const float* w_hh  = (const float*)d_in[5];
    const float* b_ih  = (const float*)d_in[6];
    const float* b_hh  = (const float*)d_in[7];
    float* out = (float*)d_out;

    cudaFuncSetAttribute(skeleton_gnn_mma,
                         cudaFuncAttributeMaxDynamicSharedMemorySize, SMEM_BYTES);

    prep_kernel<<<24, 256>>>(msg_w, msg_b, w_ih, w_hh, b_ih, b_hh);
    skeleton_gnn_mma<<<GRID_MAIN, NTHREADS, SMEM_BYTES>>>(feats, vis, out);
}

// round 5
// speedup vs baseline: 3.4982x; 1.1557x over previous
#include <cuda_runtime.h>
#include <cstdint>

typedef unsigned int u32;

#define NJ        33
#define FD        64
#define B_TOTAL   32768
#define M_TOTAL   (B_TOTAL*NJ)        // 1081344
#define TILE_M    64
#define NTILES    (M_TOTAL/TILE_M)    // 16896
#define GRID_MAIN 148
#define NTHREADS  384

#define A_STRIDE  68                  // floats per row (68*4=272B: 8 rows -> 8 distinct 16B offsets)
#define ABUF_F    (2*64*A_STRIDE)     // floats per A+H buffer pair = 8704
#define AH_BYTES  (64*A_STRIDE*4)     // byte offset of H within a buffer = 17408

// smem layout (float indices)
#define F_B       0                   // packed B fragments: 24576 floats (96KB)
#define F_A       24576               // 2 x (As 4352 + Ah 4352)
#define F_BIAS    (F_A + 2*ABUF_F)    // 41984
#define SMEM_FLOATS (F_BIAS + 256)
#define SMEM_BYTES  (SMEM_FLOATS*4)   // 168960

// ---------------- neighbor tables (self first) ----------------
__constant__ int c_nbr[NJ][4] = {
    {0,0,0,0},{1,0,0,0},{2,0,0,0},{3,0,0,0},{4,0,0,0},{5,0,0,0},{6,0,0,0},
    {7,0,0,0},{8,0,0,0},{9,0,0,0},{10,0,0,0},
    {11,12,23,13},{12,11,24,14},{13,11,15,0},{14,12,16,0},{15,13,0,0},{16,14,0,0},
    {17,0,0,0},{18,0,0,0},{19,0,0,0},{20,0,0,0},{21,0,0,0},{22,0,0,0},
    {23,11,24,25},{24,12,23,26},{25,23,27,0},{26,24,28,0},{27,25,0,0},{28,26,0,0},
    {29,0,0,0},{30,0,0,0},{31,0,0,0},{32,0,0,0}
};
__constant__ int c_cnt[NJ] = {1,1,1,1,1,1,1,1,1,1,1, 4,4,3,3,2,2, 1,1,1,1,1,1,
                              4,4,3,3,2,2, 1,1,1,1};
__constant__ float c_invcnt[NJ] = {1.f,1.f,1.f,1.f,1.f,1.f,1.f,1.f,1.f,1.f,1.f,
                                   0.25f,0.25f,1.f/3.f,1.f/3.f,0.5f,0.5f,
                                   1.f,1.f,1.f,1.f,1.f,1.f,
                                   0.25f,0.25f,1.f/3.f,1.f/3.f,0.5f,0.5f,
                                   1.f,1.f,1.f,1.f};

// packed B fragments: float4 per (ks 0..7, ds 0..1, blk 0..11, lane 0..31)
//  gate = blk>>2 (0=r,1=z,2=n); n = gate*64 + ds*32 + (blk&3)*8 + (lane>>2)
//  k0 = ks*8 + (lane&3), k1 = k0+4
//  .x=GA[n][k0] .y=GA[n][k1] .z=GH[n][k0] .w=GH[n][k1]
__device__ __align__(16) float g_Bpack[8*2*12*32*4];   // 24576 floats
__device__ float g_bias[256];                          // R | Z | IN | HN

// ---------------- helpers ----------------
__device__ __forceinline__ u32 smem_u32(const void* p) {
    u32 a;
    asm("{ .reg .u64 t; cvta.to.shared.u64 t, %1; cvt.u32.u64 %0, t; }" : "=r"(a) : "l"(p));
    return a;
}
__device__ __forceinline__ float tf32r(float x) {
    u32 u; asm("cvt.rna.tf32.f32 %0, %1;" : "=r"(u) : "f"(x));
    return __uint_as_float(u);
}
__device__ __forceinline__ float4 tf4(float4 v) {
    return make_float4(tf32r(v.x), tf32r(v.y), tf32r(v.z), tf32r(v.w));
}
__device__ __forceinline__ float tanh_ap(float x) {
    float y; asm("tanh.approx.f32 %0, %1;" : "=f"(y) : "f"(x)); return y;
}
__device__ __forceinline__ float sigm(float x) { return 0.5f * tanh_ap(0.5f * x) + 0.5f; }
__device__ __forceinline__ void mma8(float c[4], const u32 a[4], u32 b0, u32 b1) {
    asm volatile("mma.sync.aligned.m16n8k8.row.col.f32.tf32.tf32.f32 "
                 "{%0,%1,%2,%3}, {%4,%5,%6,%7}, {%8,%9}, {%0,%1,%2,%3};"
                 : "+f"(c[0]), "+f"(c[1]), "+f"(c[2]), "+f"(c[3])
                 : "r"(a[0]), "r"(a[1]), "r"(a[2]), "r"(a[3]), "r"(b0), "r"(b1));
}
__device__ __forceinline__ void ldsm4(u32 r[4], u32 addr) {
    asm volatile("ldmatrix.sync.aligned.m8n8.x4.shared.b16 {%0,%1,%2,%3}, [%4];"
                 : "=r"(r[0]), "=r"(r[1]), "=r"(r[2]), "=r"(r[3]) : "r"(addr));
}
#define BAR_SYNC(id)   asm volatile("bar.sync %0, %1;"   :: "r"(id), "r"(NTHREADS) : "memory")
#define BAR_ARRIVE(id) asm volatile("bar.arrive %0, %1;" :: "r"(id), "r"(NTHREADS) : "memory")

// ---------------- prep: fold linear chain, pack fragments, tf32-round ----------------
__global__ void prep_kernel(const float* __restrict__ msg_w, const float* __restrict__ msg_b,
                            const float* __restrict__ w_ih, const float* __restrict__ w_hh,
                            const float* __restrict__ b_ih, const float* __restrict__ b_hh) {
    int t = blockIdx.x * blockDim.x + threadIdx.x;
    if (t < 8*2*12*32) {
        int lane = t & 31;
        int blk  = (t >> 5) % 12;
        int ds   = (t >> 5) / 12 % 2;
        int ks   = t / (2*12*32);
        int g = lane >> 2, tig = lane & 3;
        int gate = blk >> 2;
        int n = gate*64 + ds*32 + (blk & 3)*8 + g;
        int k0 = ks*8 + tig, k1 = k0 + 4;
        float ga0 = 0.f, ga1 = 0.f;
        #pragma unroll 8
        for (int f = 0; f < FD; f++) {
            float wi = w_ih[n*FD + f];
            ga0 += msg_w[f*FD + k0] * wi;
            ga1 += msg_w[f*FD + k1] * wi;
        }
        ((float4*)g_Bpack)[t] = make_float4(tf32r(ga0), tf32r(ga1),
                                            tf32r(w_hh[n*FD + k0]), tf32r(w_hh[n*FD + k1]));
    }
    if (t < 192) {
        float s = 0.f;
        #pragma unroll 8
        for (int f = 0; f < FD; f++) s += msg_b[f] * w_ih[t*FD + f];
        float bA = s + b_ih[t];
        if (t < 128)      g_bias[t] = bA + b_hh[t];
        else            { g_bias[t] = bA; g_bias[t + 64] = b_hh[t]; }
    }
}

// ---------------- main persistent warp-specialized kernel ----------------
__global__ void __launch_bounds__(NTHREADS, 1)
skeleton_gnn_ws(const float* __restrict__ feats,
                const float* __restrict__ vis,
                float* __restrict__ out)
{
    extern __shared__ float sm[];
    const int tid = threadIdx.x;

    // stage packed weights + biases
    {
        const float4* gb = (const float4*)g_Bpack;
        float4* s4 = (float4*)(sm + F_B);
        #pragma unroll
        for (int i = 0; i < 16; i++) s4[tid + i*NTHREADS] = gb[tid + i*NTHREADS];
        if (tid < 256) sm[F_BIAS + tid] = g_bias[tid];
    }
    __syncthreads();

    if (tid >= 256) {
        // ================= PRODUCER (warps 8..11) =================
        const int l = tid - 256;            // 0..127
        const int row = l >> 1;             // 0..63
        const int kc4 = (l & 1) * 8;        // float4 offset within row (0 or 8)
        int iter = 0;
        for (int t = blockIdx.x; t < NTILES; t += GRID_MAIN, ++iter) {
            const int p = iter & 1;
            if (iter >= 2) BAR_SYNC(3 + p);
            float* As = sm + F_A + p*ABUF_F;
            float* Ah = As + 64*A_STRIDE;

            int gr = t*TILE_M + row;
            int b = (int)((u32)gr / 33u);
            int j = gr - b*33;
            const float4* fb = (const float4*)feats + (size_t)b * 528;   // 33*16
            const float4* srow = fb + j*16 + kc4;
            float4 s0 = srow[0], s1 = srow[1], s2 = srow[2], s3 = srow[3];
            float4 s4v = srow[4], s5 = srow[5], s6 = srow[6], s7 = srow[7];
            float* hp = Ah + row*A_STRIDE + kc4*4;
            *(float4*)(hp+0)  = tf4(s0);  *(float4*)(hp+4)  = tf4(s1);
            *(float4*)(hp+8)  = tf4(s2);  *(float4*)(hp+12) = tf4(s3);
            *(float4*)(hp+16) = tf4(s4v); *(float4*)(hp+20) = tf4(s5);
            *(float4*)(hp+24) = tf4(s6);  *(float4*)(hp+28) = tf4(s7);

            float w0 = __ldg(vis + b*NJ + j);
            float a[32];
            a[0]=w0*s0.x; a[1]=w0*s0.y; a[2]=w0*s0.z; a[3]=w0*s0.w;
            a[4]=w0*s1.x; a[5]=w0*s1.y; a[6]=w0*s1.z; a[7]=w0*s1.w;
            a[8]=w0*s2.x; a[9]=w0*s2.y; a[10]=w0*s2.z; a[11]=w0*s2.w;
            a[12]=w0*s3.x; a[13]=w0*s3.y; a[14]=w0*s3.z; a[15]=w0*s3.w;
            a[16]=w0*s4v.x; a[17]=w0*s4v.y; a[18]=w0*s4v.z; a[19]=w0*s4v.w;
            a[20]=w0*s5.x; a[21]=w0*s5.y; a[22]=w0*s5.z; a[23]=w0*s5.w;
            a[24]=w0*s6.x; a[25]=w0*s6.y; a[26]=w0*s6.z; a[27]=w0*s6.w;
            a[28]=w0*s7.x; a[29]=w0*s7.y; a[30]=w0*s7.z; a[31]=w0*s7.w;

            int cnt = c_cnt[j];
            #pragma unroll
            for (int qi = 1; qi < 4; ++qi) {
                if (qi < cnt) {
                    int nb = c_nbr[j][qi];
                    float wv = __ldg(vis + b*NJ + nb);
                    const float4* nr = fb + nb*16 + kc4;
                    #pragma unroll
                    for (int i4 = 0; i4 < 8; i4++) {
                        float4 nv = nr[i4];
                        a[i4*4+0] += wv*nv.x; a[i4*4+1] += wv*nv.y;
                        a[i4*4+2] += wv*nv.z; a[i4*4+3] += wv*nv.w;
                    }
                }
            }
            float ic = c_invcnt[j];
            float* ap = As + row*A_STRIDE + kc4*4;
            #pragma unroll
            for (int i4 = 0; i4 < 8; i4++) {
                float4 v = make_float4(a[i4*4]*ic, a[i4*4+1]*ic, a[i4*4+2]*ic, a[i4*4+3]*ic);
                *(float4*)(ap + i4*4) = tf4(v);
            }
            __threadfence_block();
            BAR_ARRIVE(1 + p);
        }
    } else {
        // ================= CONSUMER (warps 0..7) =================
        const int w    = tid >> 5;
        const int lane = tid & 31;
        const int g    = lane >> 2;
        const int tig  = lane & 3;
        const int rb   = (w & 3) * 16;      // m16 block
        const int ds   = w >> 2;            // d-slice (0: cols 0..31, 1: 32..63)
        const float* sbias = sm + F_BIAS;
        const float4* Bp4 = (const float4*)(sm + F_B);

        // per-lane ldmatrix address offsets (bytes) within a buffer
        const int mat  = lane >> 3;
        const int arow = rb + (lane & 7) + ((mat & 1) << 3);
        const u32 aoff = (u32)((arow*A_STRIDE + ((mat >> 1) << 2)) * 4);
        const u32 sa0  = smem_u32(sm + F_A) + aoff;
        const u32 sa1  = smem_u32(sm + F_A + ABUF_F) + aoff;

        int iter = 0;
        for (int t = blockIdx.x; t < NTILES; t += GRID_MAIN, ++iter) {
            const int p = iter & 1;
            BAR_SYNC(1 + p);
            const u32 abase = p ? sa1 : sa0;

            // accumulators (bias-initialized)
            float accR[4][4], accZ[4][4], accI[4][4], accH[4][4];
            #pragma unroll
            for (int blk = 0; blk < 4; blk++) {
                int col = ds*32 + blk*8 + 2*tig;
                float r0 = sbias[col],      r1 = sbias[col+1];
                float z0 = sbias[64+col],   z1 = sbias[64+col+1];
                float i0 = sbias[128+col],  i1 = sbias[128+col+1];
                float h0 = sbias[192+col],  h1 = sbias[192+col+1];
                accR[blk][0]=r0; accR[blk][1]=r1; accR[blk][2]=r0; accR[blk][3]=r1;
                accZ[blk][0]=z0; accZ[blk][1]=z1; accZ[blk][2]=z0; accZ[blk][3]=z1;
                accI[blk][0]=i0; accI[blk][1]=i1; accI[blk][2]=i0; accI[blk][3]=i1;
                accH[blk][0]=h0; accH[blk][1]=h1; accH[blk][2]=h0; accH[blk][3]=h1;
            }

            #pragma unroll
            for (int ks = 0; ks < 8; ks++) {
                u32 fa[4], fh[4];
                ldsm4(fa, abase + (u32)(ks*32));
                ldsm4(fh, abase + (u32)(ks*32) + AH_BYTES);
                const float4* bp = Bp4 + ((ks*2 + ds)*12)*32 + lane;
                #pragma unroll
                for (int blk = 0; blk < 4; blk++) {
                    float4 bw = bp[blk*32];
                    mma8(accR[blk], fa, __float_as_uint(bw.x), __float_as_uint(bw.y));
                    mma8(accR[blk], fh, __float_as_uint(bw.z), __float_as_uint(bw.w));
                }
                #pragma unroll
                for (int blk = 0; blk < 4; blk++) {
                    float4 bw = bp[(4+blk)*32];
                    mma8(accZ[blk], fa, __float_as_uint(bw.x), __float_as_uint(bw.y));
                    mma8(accZ[blk], fh, __float_as_uint(bw.z), __float_as_uint(bw.w));
                }
                #pragma unroll
                for (int blk = 0; blk < 4; blk++) {
                    float4 bw = bp[(8+blk)*32];
                    mma8(accI[blk], fa, __float_as_uint(bw.x), __float_as_uint(bw.y));
                    mma8(accH[blk], fh, __float_as_uint(bw.z), __float_as_uint(bw.w));
                }
            }
            BAR_ARRIVE(3 + p);

            // gates + direct store
            const int gr0 = t * TILE_M;
            const int r0 = gr0 + rb + g;
            const int r1 = r0 + 8;
            #pragma unroll
            for (int blk = 0; blk < 4; blk++) {
                int d0 = ds*32 + blk*8 + 2*tig;
                float2 h0 = *(const float2*)(feats + (size_t)r0*FD + d0);
                float2 h1 = *(const float2*)(feats + (size_t)r1*FD + d0);
                float2 o0, o1;
                {
                    float r = sigm(accR[blk][0]), z = sigm(accZ[blk][0]);
                    float n = tanh_ap(accI[blk][0] + r*accH[blk][0]);
                    o0.x = (1.0f - z)*n + z*h0.x;
                }
                {
                    float r = sigm(accR[blk][1]), z = sigm(accZ[blk][1]);
                    float n = tanh_ap(accI[blk][1] + r*accH[blk][1]);
                    o0.y = (1.0f - z)*n + z*h0.y;
                }
                {
                    float r = sigm(accR[blk][2]), z = sigm(accZ[blk][2]);
                    float n = tanh_ap(accI[blk][2] + r*accH[blk][2]);
                    o1.x = (1.0f - z)*n + z*h1.x;
                }
                {
                    float r = sigm(accR[blk][3]), z = sigm(accZ[blk][3]);
                    float n = tanh_ap(accI[blk][3] + r*accH[blk][3]);
                    o1.y = (1.0f - z)*n + z*h1.y;
                }
                *(float2*)(out + (size_t)r0*FD + d0) = o0;
                *(float2*)(out + (size_t)r1*FD + d0) = o1;
            }
        }
    }
}

extern "C" void kernel_launch(void* const* d_in, const int* in_sizes, int n_in,
                              void* d_out, int out_size)
{
    const float* feats = (const float*)d_in[0];
    const float* vis   = (const float*)d_in[1];
    const float* msg_w = (const float*)d_in[2];
    const float* msg_b = (const float*)d_in[3];
    const float* w_ih  = (const float*)d_in[4];
    const float* w_hh  = (const float*)d_in[5];
    const float* b_ih  = (const float*)d_in[6];
    const float* b_hh  = (const float*)d_in[7];
    float* out = (float*)d_out;

    cudaFuncSetAttribute(skeleton_gnn_ws,
                         cudaFuncAttributeMaxDynamicSharedMemorySize, SMEM_BYTES);

    prep_kernel<<<24, 256>>>(msg_w, msg_b, w_ih, w_hh, b_ih, b_hh);
    skeleton_gnn_ws<<<GRID_MAIN, NTHREADS, SMEM_BYTES>>>(feats, vis, out);
}